// round 13
// baseline (speedup 1.0000x reference)
#include <cuda_runtime.h>
#include <cuda_fp16.h>
#include <cstdint>

// ===========================================================================
// HierarchicalMemory via mma.sync fp16 (m16n8k16, fp32 accum) + ldmatrix.
//   out = softmax_m(mask(qn.mkn/T)) @ V @ Wo^T + bo,  q = X@Wk^T + bk
// Softmax with NO offset: P = exp(s), s in [-10,10] -> P in fp16 range.
// Active-slot compaction (usage>0); K6 split-K x4 + fp32 partials.
// BK=64 k-slabs (4 MMA k-steps per barrier) to amortize pipeline syncs.
// ===========================================================================

#define MQ   8192
#define HD   1024
#define MMSZ 16384

#define BM 128
#define BN 256
#define BK 64                              // fp16 elems per k-slab (128 B)
#define STAGES 3
#define RPITCH 144                         // bytes per smem row (128 data + 16 pad)
#define ATILE_B (BM * RPITCH)              // 18432
#define BTILE_B (BN * RPITCH)              // 36864
#define STAGE_B (ATILE_B + BTILE_B)        // 55296
#define SMEM_TOTAL (STAGES * STAGE_B)      // 165888
#define SPLITK 4

// ---- scratch ----
__device__ __half g_mkn[(size_t)MMSZ * HD];
__device__ __half g_q  [(size_t)MQ * HD];
__device__ float  g_qs [MQ];
__device__ __half g_P  [(size_t)MQ * MMSZ];
__device__ float  g_rs [MQ];
__device__ __half g_ret[(size_t)MQ * HD];
__device__ __half g_vt [(size_t)HD * MMSZ];
__device__ __half g_ht [(size_t)MQ * HD];
__device__ __half g_wk [(size_t)HD * HD];
__device__ __half g_wo [(size_t)HD * HD];
__device__ float  g_part[(size_t)SPLITK * MQ * HD];
__device__ int    g_idx[MMSZ];
__device__ int    g_mact;
__device__ int    g_mpad;

enum { EPI_BIAS = 0, EPI_EXPMASK = 1, EPI_NONE = 2 };

// ---------------------------------------------------------------------------
__device__ __forceinline__ uint32_t smem_u32(const void* p) {
    uint32_t a;
    asm("{ .reg .u64 t; cvta.to.shared.u64 t, %1; cvt.u32.u64 %0, t; }" : "=r"(a) : "l"(p));
    return a;
}
#define CP_ASYNC16(dst, src) \
    asm volatile("cp.async.cg.shared.global [%0], [%1], 16;" :: "r"(dst), "l"(src) : "memory")
#define CP_COMMIT() asm volatile("cp.async.commit_group;" ::: "memory")
#define CP_WAIT1()  asm volatile("cp.async.wait_group 1;" ::: "memory")

__device__ __forceinline__ void mma16(float* d, const uint32_t* a, const uint32_t* b) {
    asm volatile(
        "mma.sync.aligned.m16n8k16.row.col.f32.f16.f16.f32 "
        "{%0,%1,%2,%3}, {%4,%5,%6,%7}, {%8,%9}, {%0,%1,%2,%3};"
        : "+f"(d[0]), "+f"(d[1]), "+f"(d[2]), "+f"(d[3])
        : "r"(a[0]), "r"(a[1]), "r"(a[2]), "r"(a[3]), "r"(b[0]), "r"(b[1]));
}
__device__ __forceinline__ void ldsm4(uint32_t* r, uint32_t a) {
    asm volatile("ldmatrix.sync.aligned.m8n8.x4.shared.b16 {%0,%1,%2,%3}, [%4];"
        : "=r"(r[0]), "=r"(r[1]), "=r"(r[2]), "=r"(r[3]) : "r"(a));
}

// ---------------------------------------------------------------------------
// C[M,N] = A[M,K] . B[N,K]^T  (NT, K-major fp16, fp32 accumulate)
// 8 warps 2x4, 64x64 warp tiles, ldmatrix feeds, 3-stage cp.async pipeline,
// BK=64 slabs (4 kk-steps per barrier).
// OUTH: store fp16 (rounding fused); else fp32.
// EPI_NONE+DYNK: split-K chunk (blockIdx.z), partial -> C + z*MQ*HD (fp32).
// ---------------------------------------------------------------------------
template <int EPI, bool OUTH, bool DYNK>
__global__ __launch_bounds__(256)
void gemm_mma(const __half* __restrict__ A, int lda,
              const __half* __restrict__ B, int ldb,
              void* __restrict__ Cv, int ldc,
              int K, const float* __restrict__ aux,
              float* __restrict__ rowsum, int nx) {
    const int mtb = nx ? blockIdx.y : blockIdx.x;
    const int ntb = nx ? blockIdx.x : blockIdx.y;
    const int m0 = mtb * BM, n0 = ntb * BN;

    if (EPI == EPI_EXPMASK && n0 >= g_mpad) return;
    int Keff = DYNK ? (g_mpad >> 2) : K;
    int koff = 0;
    float* Cf = (float*)Cv;
    __half* Ch = (__half*)Cv;
    if (EPI == EPI_NONE && DYNK) {
        koff = blockIdx.z * Keff;
        Cf += (size_t)blockIdx.z * MQ * HD;
    }
    const int n_it = Keff / BK;

    extern __shared__ char smem[];
    const uint32_t sb = smem_u32(smem);
    const int tid  = threadIdx.x;
    const int wid  = tid >> 5, lane = tid & 31;
    const int g    = lane >> 2, t = lane & 3;
    const int wm   = wid >> 2, wn = wid & 3;      // 2 x 4 warps, 64x64 tiles

    float acc[4][8][4];
    #pragma unroll
    for (int i = 0; i < 4; i++)
        #pragma unroll
        for (int j = 0; j < 8; j++)
            #pragma unroll
            for (int r = 0; r < 4; r++) acc[i][j][r] = 0.0f;

    // ldmatrix per-lane byte offsets within a stage tile (144 B row pitch)
    const uint32_t a_off = (uint32_t)((wm * 64 + (lane & 15)) * RPITCH + ((lane >> 4) & 1) * 16);
    const uint32_t b_off = (uint32_t)((wn * 64 + (lane & 7) + ((lane >> 4) & 1) * 8) * RPITCH +
                                      ((lane >> 3) & 1) * 16);

    // loaders: rows have 8 x 16B chunks. A: 128 rows (4 chunks/thread),
    // B: 256 rows (8 chunks/thread).
    const int arow = tid >> 1;
    const int aq   = (tid & 1) * 4;

    auto issue = [&](int it) {
        if (it < n_it) {
            const int s = it % STAGES;
            const int kt = koff + it * BK;
            const uint32_t da = sb + s * STAGE_B;
            const uint32_t db = da + ATILE_B;
            const __half* ga = A + (size_t)(m0 + arow) * lda + kt;
            const __half* gb = B + (size_t)(n0 + tid) * ldb + kt;
            #pragma unroll
            for (int c = 0; c < 4; c++)
                CP_ASYNC16(da + arow * RPITCH + (aq + c) * 16, ga + (aq + c) * 8);
            #pragma unroll
            for (int c = 0; c < 8; c++)
                CP_ASYNC16(db + tid * RPITCH + c * 16, gb + c * 8);
        }
        CP_COMMIT();
    };

    issue(0);
    issue(1);
    CP_WAIT1();            // group 0 resident
    __syncthreads();

    for (int it = 0; it < n_it; ++it) {
        issue(it + 2);     // writes slot (it-1)%3: consumed before prior barrier

        const int s = it % STAGES;
        const uint32_t As = sb + s * STAGE_B + a_off;
        const uint32_t Bs = sb + s * STAGE_B + ATILE_B + b_off;

        #pragma unroll
        for (int kk = 0; kk < 4; kk++) {     // four K=16 steps per 64-elem slab
            uint32_t af[4][4], bf[8][2];
            #pragma unroll
            for (int mt = 0; mt < 4; mt++)
                ldsm4(af[mt], As + mt * (16 * RPITCH) + kk * 32);
            #pragma unroll
            for (int np = 0; np < 4; np++)
                ldsm4(&bf[2 * np][0], Bs + np * (16 * RPITCH) + kk * 32);
            #pragma unroll
            for (int mt = 0; mt < 4; mt++)
                #pragma unroll
                for (int nt = 0; nt < 8; nt++)
                    mma16(acc[mt][nt], af[mt], bf[nt]);
        }

        CP_WAIT1();        // group it+1 resident
        __syncthreads();
    }

    // ---------------- epilogue ----------------
    const int mrow = m0 + wm * 64;
    const int ncol = n0 + wn * 64;
    const int mact = (EPI == EPI_EXPMASK) ? g_mact : 0;

    float bia[8][2];
    if (EPI == EPI_BIAS) {
        #pragma unroll
        for (int nt = 0; nt < 8; nt++) {
            const int c = ncol + nt * 8 + 2 * t;
            bia[nt][0] = __ldg(aux + c);
            bia[nt][1] = __ldg(aux + c + 1);
        }
    }
    float rsv[4][2];
    if (EPI == EPI_EXPMASK) {
        #pragma unroll
        for (int mt = 0; mt < 4; mt++)
            #pragma unroll
            for (int h = 0; h < 2; h++)
                rsv[mt][h] = __ldg(aux + mrow + mt * 16 + g + h * 8);
    }

    float rsum[4][2];
    #pragma unroll
    for (int mt = 0; mt < 4; mt++) { rsum[mt][0] = 0.0f; rsum[mt][1] = 0.0f; }

    #pragma unroll
    for (int mt = 0; mt < 4; mt++) {
        #pragma unroll
        for (int h = 0; h < 2; h++) {
            const int r = mrow + mt * 16 + g + h * 8;
            #pragma unroll
            for (int nt = 0; nt < 8; nt++) {
                const int c = ncol + nt * 8 + 2 * t;
                float v0 = acc[mt][nt][2 * h + 0];
                float v1 = acc[mt][nt][2 * h + 1];
                if (EPI == EPI_BIAS) { v0 += bia[nt][0]; v1 += bia[nt][1]; }
                if (EPI == EPI_EXPMASK) {
                    const float rs = rsv[mt][h];
                    v0 = (c     < mact) ? __expf(v0 * rs) : 0.0f;   // P = exp(s)
                    v1 = (c + 1 < mact) ? __expf(v1 * rs) : 0.0f;
                }
                if (OUTH) {
                    __half2 hv = __floats2half2_rn(v0, v1);
                    if (EPI == EPI_EXPMASK) {        // rowsum of ROUNDED values
                        float2 bb = __half22float2(hv);
                        rsum[mt][h] += bb.x + bb.y;
                    }
                    *(__half2*)(Ch + (size_t)r * ldc + c) = hv;
                } else {
                    *(float2*)(Cf + (size_t)r * ldc + c) = make_float2(v0, v1);
                }
            }
        }
    }

    if (EPI == EPI_EXPMASK) {
        #pragma unroll
        for (int mt = 0; mt < 4; mt++)
            #pragma unroll
            for (int h = 0; h < 2; h++) {
                float v = rsum[mt][h];
                v += __shfl_xor_sync(0xffffffffu, v, 1);
                v += __shfl_xor_sync(0xffffffffu, v, 2);
                if (t == 0) atomicAdd(rowsum + mrow + mt * 16 + g + h * 8, v);
            }
    }
}

// ---------------------------------------------------------------------------
// split-K reduce: ret = fp16((p0+p1+p2+p3) / rowsum)
// ---------------------------------------------------------------------------
__global__ void reduce_splitk(const float* __restrict__ part,
                              const float* __restrict__ rowsum,
                              __half* __restrict__ out) {
    const size_t S = (size_t)MQ * HD;
    const size_t i = ((size_t)blockIdx.x * 256 + threadIdx.x) * 4;
    float4 a = *(const float4*)(part + i);
    float4 b = *(const float4*)(part + S + i);
    float4 c = *(const float4*)(part + 2 * S + i);
    float4 d = *(const float4*)(part + 3 * S + i);
    const float f = 1.0f / __ldg(rowsum + (int)(i / HD));
    __half2* o = (__half2*)(out + i);
    o[0] = __floats2half2_rn((a.x + b.x + c.x + d.x) * f, (a.y + b.y + c.y + d.y) * f);
    o[1] = __floats2half2_rn((a.z + b.z + c.z + d.z) * f, (a.w + b.w + c.w + d.w) * f);
}

// ---------------------------------------------------------------------------
// compaction: order-preserving scan of usage>0 into g_idx; sets g_mact/g_mpad
// ---------------------------------------------------------------------------
__global__ void compact_mask(const int* __restrict__ usage) {
    const int tid = threadIdx.x;
    const int base = tid * (MMSZ / 256);
    int cnt = 0;
    #pragma unroll 8
    for (int i = 0; i < MMSZ / 256; i++) cnt += (usage[base + i] > 0);
    int v = cnt;
    const int lane = tid & 31, w = tid >> 5;
    #pragma unroll
    for (int o = 1; o < 32; o <<= 1) {
        int n = __shfl_up_sync(0xffffffffu, v, o);
        if (lane >= o) v += n;
    }
    __shared__ int ws[8];
    if (lane == 31) ws[w] = v;
    __syncthreads();
    if (tid == 0) {
        int acc = 0;
        #pragma unroll
        for (int i = 0; i < 8; i++) { int x = ws[i]; ws[i] = acc; acc += x; }
        g_mact = acc;
        g_mpad = (acc + BN - 1) & ~(BN - 1);   // mult of 256 -> K6 chunks mult of 64
    }
    __syncthreads();
    int off = ws[w] + v - cnt;
    for (int i = 0; i < MMSZ / 256; i++)
        if (usage[base + i] > 0) g_idx[off++] = base + i;
}

// ---------------------------------------------------------------------------
__device__ __forceinline__ float blk_reduce_256(float v) {
    #pragma unroll
    for (int o = 16; o > 0; o >>= 1) v += __shfl_xor_sync(0xffffffffu, v, o);
    __shared__ float sm[8];
    int w = threadIdx.x >> 5, l = threadIdx.x & 31;
    if (l == 0) sm[w] = v;
    __syncthreads();
    float r = 0.0f;
    if (w == 0) {
        r = (l < 8) ? sm[l] : 0.0f;
        #pragma unroll
        for (int o = 4; o > 0; o >>= 1) r += __shfl_xor_sync(0xffffffffu, r, o);
    }
    return r;
}

// mkn_c[j,:] = fp16(l2norm(mkeys[idx[j],:])); zeros for pad rows
__global__ void l2norm_gather(const float* __restrict__ in, __half* __restrict__ out) {
    const int j = blockIdx.x;
    if (j >= g_mpad) return;
    const size_t doff = (size_t)j * HD + threadIdx.x * 4;
    __half2* o = (__half2*)(out + doff);
    if (j >= g_mact) {
        o[0] = __floats2half2_rn(0.f, 0.f);
        o[1] = __floats2half2_rn(0.f, 0.f);
        return;
    }
    const size_t soff = (size_t)g_idx[j] * HD + threadIdx.x * 4;
    float4 v = *(const float4*)(in + soff);
    float s = v.x * v.x + v.y * v.y + v.z * v.z + v.w * v.w;
    s = blk_reduce_256(s);
    __shared__ float sc;
    if (threadIdx.x == 0) sc = rsqrtf(s + 1e-6f);
    __syncthreads();
    const float k = sc;
    o[0] = __floats2half2_rn(v.x * k, v.y * k);
    o[1] = __floats2half2_rn(v.z * k, v.w * k);
}

// vt[h, j] = fp16(V[idx[j], h]); zeros for pad columns
__global__ void transpose_gather(const float* __restrict__ src, __half* __restrict__ dst) {
    __shared__ float tl[32][33];
    const int n0 = blockIdx.x * 32, k0 = blockIdx.y * 32;
    if (k0 >= g_mpad) return;
    const int tx = threadIdx.x, ty = threadIdx.y;
    const int mact = g_mact;
    #pragma unroll
    for (int j = 0; j < 4; j++) {
        const int k = k0 + ty + 8 * j;
        float v = 0.0f;
        if (k < mact) v = src[(size_t)g_idx[k] * HD + n0 + tx];
        tl[ty + 8 * j][tx] = v;
    }
    __syncthreads();
    #pragma unroll
    for (int j = 0; j < 4; j++)
        dst[(size_t)(n0 + ty + 8 * j) * MMSZ + k0 + tx] = __float2half_rn(tl[tx][ty + 8 * j]);
}

// per-row scale of fp16 q: rsqrt(sumsq+eps) * 10
__global__ void row_qscale(const __half* __restrict__ q, float* __restrict__ scale) {
    const __half2* p = (const __half2*)(q + (size_t)blockIdx.x * HD) + threadIdx.x * 2;
    float2 a = __half22float2(p[0]);
    float2 b = __half22float2(p[1]);
    float s = a.x * a.x + a.y * a.y + b.x * b.x + b.y * b.y;
    s = blk_reduce_256(s);
    if (threadIdx.x == 0) scale[blockIdx.x] = rsqrtf(s + 1e-6f) * 10.0f;
}

// fp32 -> fp16 copy
__global__ void half_copy(const float* __restrict__ in, __half* __restrict__ out) {
    size_t i = ((size_t)blockIdx.x * 256 + threadIdx.x) * 4;
    float4 v = *(const float4*)(in + i);
    __half2* o = (__half2*)(out + i);
    o[0] = __floats2half2_rn(v.x, v.y);
    o[1] = __floats2half2_rn(v.z, v.w);
}

// ---------------------------------------------------------------------------

extern "C" void kernel_launch(void* const* d_in, const int* in_sizes, int n_in,
                              void* d_out, int out_size) {
    const float* hidden = (const float*)d_in[0];
    const float* Wk     = (const float*)d_in[1];
    const float* bk     = (const float*)d_in[2];
    const float* Wo     = (const float*)d_in[5];
    const float* bo     = (const float*)d_in[6];
    const float* mkeys  = (const float*)d_in[7];
    const float* mvals  = (const float*)d_in[8];
    const int*   usage  = (const int*)d_in[9];

    __half *mkn, *q, *P, *ret, *vt, *ht, *wk, *wo;
    float *qs, *rs, *part;
    cudaGetSymbolAddress((void**)&mkn, g_mkn);
    cudaGetSymbolAddress((void**)&q,   g_q);
    cudaGetSymbolAddress((void**)&qs,  g_qs);
    cudaGetSymbolAddress((void**)&P,   g_P);
    cudaGetSymbolAddress((void**)&rs,  g_rs);
    cudaGetSymbolAddress((void**)&ret, g_ret);
    cudaGetSymbolAddress((void**)&vt,  g_vt);
    cudaGetSymbolAddress((void**)&ht,  g_ht);
    cudaGetSymbolAddress((void**)&wk,  g_wk);
    cudaGetSymbolAddress((void**)&wo,  g_wo);
    cudaGetSymbolAddress((void**)&part, g_part);

    cudaFuncSetAttribute(gemm_mma<EPI_BIAS, true, false>,    cudaFuncAttributeMaxDynamicSharedMemorySize, SMEM_TOTAL);
    cudaFuncSetAttribute(gemm_mma<EPI_EXPMASK, true, false>, cudaFuncAttributeMaxDynamicSharedMemorySize, SMEM_TOTAL);
    cudaFuncSetAttribute(gemm_mma<EPI_NONE, false, true>,    cudaFuncAttributeMaxDynamicSharedMemorySize, SMEM_TOTAL);
    cudaFuncSetAttribute(gemm_mma<EPI_BIAS, false, false>,   cudaFuncAttributeMaxDynamicSharedMemorySize, SMEM_TOTAL);

    // compaction + fp16 operand preparation
    compact_mask<<<1, 256>>>(usage);
    half_copy<<<(MQ * HD) / 1024, 256>>>(hidden, ht);
    half_copy<<<(HD * HD) / 1024, 256>>>(Wk, wk);
    half_copy<<<(HD * HD) / 1024, 256>>>(Wo, wo);
    l2norm_gather<<<MMSZ, 256>>>(mkeys, mkn);
    transpose_gather<<<dim3(HD / 32, MMSZ / 32), dim3(32, 8)>>>(mvals, vt);
    cudaMemsetAsync(rs, 0, MQ * sizeof(float));

    // K2: q = fp16(X @ Wk^T + bk)
    gemm_mma<EPI_BIAS, true, false><<<dim3(MQ / BM, HD / BN), 256, SMEM_TOTAL>>>(
        ht, HD, wk, HD, q, HD, HD, bk, nullptr, 0);

    // K3: per-row query scale rsqrt(sumsq+eps)*10
    row_qscale<<<MQ, 256>>>(q, qs);

    // K4: P = fp16((col<mact) ? exp(dot*qs) : 0)  (+fused rowsums of rounded P)
    gemm_mma<EPI_EXPMASK, true, false><<<dim3(MQ / BM, MMSZ / BN), 256, SMEM_TOTAL>>>(
        q, HD, mkn, HD, P, MMSZ, HD, qs, rs, 0);

    // K6: split-K x4 fp32 partials of P @ Vt^T  (~99% wave util)
    gemm_mma<EPI_NONE, false, true><<<dim3(HD / BN, MQ / BM, SPLITK), 256, SMEM_TOTAL>>>(
        P, MMSZ, vt, MMSZ, part, HD, 0, nullptr, nullptr, 1);

    // K6b: ret = fp16((sum of partials) / rowsum)
    reduce_splitk<<<(MQ * HD) / 1024, 256>>>(part, rs, ret);

    // K7: out = ret @ Wo^T + bo  (fp32 out)
    gemm_mma<EPI_BIAS, false, false><<<dim3(MQ / BM, HD / BN), 256, SMEM_TOTAL>>>(
        ret, HD, wo, HD, (float*)d_out, HD, HD, bo, nullptr, 0);
}

// round 14
// speedup vs baseline: 1.0215x; 1.0215x over previous
#include <cuda_runtime.h>
#include <cuda_fp16.h>
#include <cstdint>

// ===========================================================================
// HierarchicalMemory via mma.sync fp16 (m16n8k16, fp32 accum) + ldmatrix.
//   out = softmax_m(mask(qn.mkn/T)) @ V @ Wo^T + bo,  q = X@Wk^T + bk
// Softmax with NO offset: P = exp(s), s in [-10,10] -> P in fp16 range.
// Active-slot compaction (usage>0); K6 split-K x4 + fp32 partials.
// R14: fork-join dual-stream prep (gathers overlap K2) + fused prep launches.
// ===========================================================================

#define MQ   8192
#define HD   1024
#define MMSZ 16384

#define BM 128
#define BN 256
#define BK 64                              // fp16 elems per k-slab (128 B)
#define STAGES 3
#define RPITCH 144                         // bytes per smem row (128 data + 16 pad)
#define ATILE_B (BM * RPITCH)              // 18432
#define BTILE_B (BN * RPITCH)              // 36864
#define STAGE_B (ATILE_B + BTILE_B)        // 55296
#define SMEM_TOTAL (STAGES * STAGE_B)      // 165888
#define SPLITK 4

// ---- scratch ----
__device__ __half g_mkn[(size_t)MMSZ * HD];
__device__ __half g_q  [(size_t)MQ * HD];
__device__ float  g_qs [MQ];
__device__ __half g_P  [(size_t)MQ * MMSZ];
__device__ float  g_rs [MQ];
__device__ __half g_ret[(size_t)MQ * HD];
__device__ __half g_vt [(size_t)HD * MMSZ];
__device__ __half g_ht [(size_t)MQ * HD];
__device__ __half g_wk [(size_t)HD * HD];
__device__ __half g_wo [(size_t)HD * HD];
__device__ float  g_part[(size_t)SPLITK * MQ * HD];
__device__ int    g_idx[MMSZ];
__device__ int    g_mact;
__device__ int    g_mpad;

enum { EPI_BIAS = 0, EPI_EXPMASK = 1, EPI_NONE = 2 };

// ---------------------------------------------------------------------------
__device__ __forceinline__ uint32_t smem_u32(const void* p) {
    uint32_t a;
    asm("{ .reg .u64 t; cvta.to.shared.u64 t, %1; cvt.u32.u64 %0, t; }" : "=r"(a) : "l"(p));
    return a;
}
#define CP_ASYNC16(dst, src) \
    asm volatile("cp.async.cg.shared.global [%0], [%1], 16;" :: "r"(dst), "l"(src) : "memory")
#define CP_COMMIT() asm volatile("cp.async.commit_group;" ::: "memory")
#define CP_WAIT1()  asm volatile("cp.async.wait_group 1;" ::: "memory")

__device__ __forceinline__ void mma16(float* d, const uint32_t* a, const uint32_t* b) {
    asm volatile(
        "mma.sync.aligned.m16n8k16.row.col.f32.f16.f16.f32 "
        "{%0,%1,%2,%3}, {%4,%5,%6,%7}, {%8,%9}, {%0,%1,%2,%3};"
        : "+f"(d[0]), "+f"(d[1]), "+f"(d[2]), "+f"(d[3])
        : "r"(a[0]), "r"(a[1]), "r"(a[2]), "r"(a[3]), "r"(b[0]), "r"(b[1]));
}
__device__ __forceinline__ void ldsm4(uint32_t* r, uint32_t a) {
    asm volatile("ldmatrix.sync.aligned.m8n8.x4.shared.b16 {%0,%1,%2,%3}, [%4];"
        : "=r"(r[0]), "=r"(r[1]), "=r"(r[2]), "=r"(r[3]) : "r"(a));
}

// ---------------------------------------------------------------------------
// C[M,N] = A[M,K] . B[N,K]^T  (NT, K-major fp16, fp32 accumulate)
// 8 warps 2x4, 64x64 warp tiles, ldmatrix feeds, 3-stage cp.async pipeline,
// BK=64 slabs (4 kk-steps per barrier).
// OUTH: store fp16 (rounding fused); else fp32.
// EPI_NONE+DYNK: split-K chunk (blockIdx.z), partial -> C + z*MQ*HD (fp32).
// ---------------------------------------------------------------------------
template <int EPI, bool OUTH, bool DYNK>
__global__ __launch_bounds__(256)
void gemm_mma(const __half* __restrict__ A, int lda,
              const __half* __restrict__ B, int ldb,
              void* __restrict__ Cv, int ldc,
              int K, const float* __restrict__ aux,
              float* __restrict__ rowsum, int nx) {
    const int mtb = nx ? blockIdx.y : blockIdx.x;
    const int ntb = nx ? blockIdx.x : blockIdx.y;
    const int m0 = mtb * BM, n0 = ntb * BN;

    if (EPI == EPI_EXPMASK && n0 >= g_mpad) return;
    int Keff = DYNK ? (g_mpad >> 2) : K;
    int koff = 0;
    float* Cf = (float*)Cv;
    __half* Ch = (__half*)Cv;
    if (EPI == EPI_NONE && DYNK) {
        koff = blockIdx.z * Keff;
        Cf += (size_t)blockIdx.z * MQ * HD;
    }
    const int n_it = Keff / BK;

    extern __shared__ char smem[];
    const uint32_t sb = smem_u32(smem);
    const int tid  = threadIdx.x;
    const int wid  = tid >> 5, lane = tid & 31;
    const int g    = lane >> 2, t = lane & 3;
    const int wm   = wid >> 2, wn = wid & 3;      // 2 x 4 warps, 64x64 tiles

    float acc[4][8][4];
    #pragma unroll
    for (int i = 0; i < 4; i++)
        #pragma unroll
        for (int j = 0; j < 8; j++)
            #pragma unroll
            for (int r = 0; r < 4; r++) acc[i][j][r] = 0.0f;

    // ldmatrix per-lane byte offsets within a stage tile (144 B row pitch)
    const uint32_t a_off = (uint32_t)((wm * 64 + (lane & 15)) * RPITCH + ((lane >> 4) & 1) * 16);
    const uint32_t b_off = (uint32_t)((wn * 64 + (lane & 7) + ((lane >> 4) & 1) * 8) * RPITCH +
                                      ((lane >> 3) & 1) * 16);

    // loaders: rows have 8 x 16B chunks. A: 128 rows (4 chunks/thread),
    // B: 256 rows (8 chunks/thread).
    const int arow = tid >> 1;
    const int aq   = (tid & 1) * 4;

    auto issue = [&](int it) {
        if (it < n_it) {
            const int s = it % STAGES;
            const int kt = koff + it * BK;
            const uint32_t da = sb + s * STAGE_B;
            const uint32_t db = da + ATILE_B;
            const __half* ga = A + (size_t)(m0 + arow) * lda + kt;
            const __half* gb = B + (size_t)(n0 + tid) * ldb + kt;
            #pragma unroll
            for (int c = 0; c < 4; c++)
                CP_ASYNC16(da + arow * RPITCH + (aq + c) * 16, ga + (aq + c) * 8);
            #pragma unroll
            for (int c = 0; c < 8; c++)
                CP_ASYNC16(db + tid * RPITCH + c * 16, gb + c * 8);
        }
        CP_COMMIT();
    };

    issue(0);
    issue(1);
    CP_WAIT1();            // group 0 resident
    __syncthreads();

    for (int it = 0; it < n_it; ++it) {
        issue(it + 2);     // writes slot (it-1)%3: consumed before prior barrier

        const int s = it % STAGES;
        const uint32_t As = sb + s * STAGE_B + a_off;
        const uint32_t Bs = sb + s * STAGE_B + ATILE_B + b_off;

        #pragma unroll
        for (int kk = 0; kk < 4; kk++) {     // four K=16 steps per 64-elem slab
            uint32_t af[4][4], bf[8][2];
            #pragma unroll
            for (int mt = 0; mt < 4; mt++)
                ldsm4(af[mt], As + mt * (16 * RPITCH) + kk * 32);
            #pragma unroll
            for (int np = 0; np < 4; np++)
                ldsm4(&bf[2 * np][0], Bs + np * (16 * RPITCH) + kk * 32);
            #pragma unroll
            for (int mt = 0; mt < 4; mt++)
                #pragma unroll
                for (int nt = 0; nt < 8; nt++)
                    mma16(acc[mt][nt], af[mt], bf[nt]);
        }

        CP_WAIT1();        // group it+1 resident
        __syncthreads();
    }

    // ---------------- epilogue ----------------
    const int mrow = m0 + wm * 64;
    const int ncol = n0 + wn * 64;
    const int mact = (EPI == EPI_EXPMASK) ? g_mact : 0;

    float bia[8][2];
    if (EPI == EPI_BIAS) {
        #pragma unroll
        for (int nt = 0; nt < 8; nt++) {
            const int c = ncol + nt * 8 + 2 * t;
            bia[nt][0] = __ldg(aux + c);
            bia[nt][1] = __ldg(aux + c + 1);
        }
    }
    float rsv[4][2];
    if (EPI == EPI_EXPMASK) {
        #pragma unroll
        for (int mt = 0; mt < 4; mt++)
            #pragma unroll
            for (int h = 0; h < 2; h++)
                rsv[mt][h] = __ldg(aux + mrow + mt * 16 + g + h * 8);
    }

    float rsum[4][2];
    #pragma unroll
    for (int mt = 0; mt < 4; mt++) { rsum[mt][0] = 0.0f; rsum[mt][1] = 0.0f; }

    #pragma unroll
    for (int mt = 0; mt < 4; mt++) {
        #pragma unroll
        for (int h = 0; h < 2; h++) {
            const int r = mrow + mt * 16 + g + h * 8;
            #pragma unroll
            for (int nt = 0; nt < 8; nt++) {
                const int c = ncol + nt * 8 + 2 * t;
                float v0 = acc[mt][nt][2 * h + 0];
                float v1 = acc[mt][nt][2 * h + 1];
                if (EPI == EPI_BIAS) { v0 += bia[nt][0]; v1 += bia[nt][1]; }
                if (EPI == EPI_EXPMASK) {
                    const float rs = rsv[mt][h];
                    v0 = (c     < mact) ? __expf(v0 * rs) : 0.0f;   // P = exp(s)
                    v1 = (c + 1 < mact) ? __expf(v1 * rs) : 0.0f;
                }
                if (OUTH) {
                    __half2 hv = __floats2half2_rn(v0, v1);
                    if (EPI == EPI_EXPMASK) {        // rowsum of ROUNDED values
                        float2 bb = __half22float2(hv);
                        rsum[mt][h] += bb.x + bb.y;
                    }
                    *(__half2*)(Ch + (size_t)r * ldc + c) = hv;
                } else {
                    *(float2*)(Cf + (size_t)r * ldc + c) = make_float2(v0, v1);
                }
            }
        }
    }

    if (EPI == EPI_EXPMASK) {
        #pragma unroll
        for (int mt = 0; mt < 4; mt++)
            #pragma unroll
            for (int h = 0; h < 2; h++) {
                float v = rsum[mt][h];
                v += __shfl_xor_sync(0xffffffffu, v, 1);
                v += __shfl_xor_sync(0xffffffffu, v, 2);
                if (t == 0) atomicAdd(rowsum + mrow + mt * 16 + g + h * 8, v);
            }
    }
}

// ---------------------------------------------------------------------------
// split-K reduce: ret = fp16((p0+p1+p2+p3) / rowsum)
// ---------------------------------------------------------------------------
__global__ void reduce_splitk(const float* __restrict__ part,
                              const float* __restrict__ rowsum,
                              __half* __restrict__ out) {
    const size_t S = (size_t)MQ * HD;
    const size_t i = ((size_t)blockIdx.x * 256 + threadIdx.x) * 4;
    float4 a = *(const float4*)(part + i);
    float4 b = *(const float4*)(part + S + i);
    float4 c = *(const float4*)(part + 2 * S + i);
    float4 d = *(const float4*)(part + 3 * S + i);
    const float f = 1.0f / __ldg(rowsum + (int)(i / HD));
    __half2* o = (__half2*)(out + i);
    o[0] = __floats2half2_rn((a.x + b.x + c.x + d.x) * f, (a.y + b.y + c.y + d.y) * f);
    o[1] = __floats2half2_rn((a.z + b.z + c.z + d.z) * f, (a.w + b.w + c.w + d.w) * f);
}

// ---------------------------------------------------------------------------
// compaction: order-preserving scan of usage>0 into g_idx; sets g_mact/g_mpad.
// Also zeroes the rowsum accumulator (fused former memset).
// ---------------------------------------------------------------------------
__global__ void compact_mask(const int* __restrict__ usage, float* __restrict__ rs) {
    const int tid = threadIdx.x;
    #pragma unroll
    for (int i = 0; i < MQ / 256; i++) rs[tid + i * 256] = 0.0f;

    const int base = tid * (MMSZ / 256);
    int cnt = 0;
    #pragma unroll 8
    for (int i = 0; i < MMSZ / 256; i++) cnt += (usage[base + i] > 0);
    int v = cnt;
    const int lane = tid & 31, w = tid >> 5;
    #pragma unroll
    for (int o = 1; o < 32; o <<= 1) {
        int n = __shfl_up_sync(0xffffffffu, v, o);
        if (lane >= o) v += n;
    }
    __shared__ int ws[8];
    if (lane == 31) ws[w] = v;
    __syncthreads();
    if (tid == 0) {
        int acc = 0;
        #pragma unroll
        for (int i = 0; i < 8; i++) { int x = ws[i]; ws[i] = acc; acc += x; }
        g_mact = acc;
        g_mpad = (acc + BN - 1) & ~(BN - 1);   // mult of 256 -> K6 chunks mult of 64
    }
    __syncthreads();
    int off = ws[w] + v - cnt;
    for (int i = 0; i < MMSZ / 256; i++)
        if (usage[base + i] > 0) g_idx[off++] = base + i;
}

// ---------------------------------------------------------------------------
__device__ __forceinline__ float blk_reduce_256(float v) {
    #pragma unroll
    for (int o = 16; o > 0; o >>= 1) v += __shfl_xor_sync(0xffffffffu, v, o);
    __shared__ float sm[8];
    int w = threadIdx.x >> 5, l = threadIdx.x & 31;
    if (l == 0) sm[w] = v;
    __syncthreads();
    float r = 0.0f;
    if (w == 0) {
        r = (l < 8) ? sm[l] : 0.0f;
        #pragma unroll
        for (int o = 4; o > 0; o >>= 1) r += __shfl_xor_sync(0xffffffffu, r, o);
    }
    return r;
}

// mkn_c[j,:] = fp16(l2norm(mkeys[idx[j],:])); zeros for pad rows
__global__ void l2norm_gather(const float* __restrict__ in, __half* __restrict__ out) {
    const int j = blockIdx.x;
    if (j >= g_mpad) return;
    const size_t doff = (size_t)j * HD + threadIdx.x * 4;
    __half2* o = (__half2*)(out + doff);
    if (j >= g_mact) {
        o[0] = __floats2half2_rn(0.f, 0.f);
        o[1] = __floats2half2_rn(0.f, 0.f);
        return;
    }
    const size_t soff = (size_t)g_idx[j] * HD + threadIdx.x * 4;
    float4 v = *(const float4*)(in + soff);
    float s = v.x * v.x + v.y * v.y + v.z * v.z + v.w * v.w;
    s = blk_reduce_256(s);
    __shared__ float sc;
    if (threadIdx.x == 0) sc = rsqrtf(s + 1e-6f);
    __syncthreads();
    const float k = sc;
    o[0] = __floats2half2_rn(v.x * k, v.y * k);
    o[1] = __floats2half2_rn(v.z * k, v.w * k);
}

// vt[h, j] = fp16(V[idx[j], h]); zeros for pad columns
__global__ void transpose_gather(const float* __restrict__ src, __half* __restrict__ dst) {
    __shared__ float tl[32][33];
    const int n0 = blockIdx.x * 32, k0 = blockIdx.y * 32;
    if (k0 >= g_mpad) return;
    const int tx = threadIdx.x, ty = threadIdx.y;
    const int mact = g_mact;
    #pragma unroll
    for (int j = 0; j < 4; j++) {
        const int k = k0 + ty + 8 * j;
        float v = 0.0f;
        if (k < mact) v = src[(size_t)g_idx[k] * HD + n0 + tx];
        tl[ty + 8 * j][tx] = v;
    }
    __syncthreads();
    #pragma unroll
    for (int j = 0; j < 4; j++)
        dst[(size_t)(n0 + ty + 8 * j) * MMSZ + k0 + tx] = __float2half_rn(tl[tx][ty + 8 * j]);
}

// per-row scale of fp16 q: rsqrt(sumsq+eps) * 10
__global__ void row_qscale(const __half* __restrict__ q, float* __restrict__ scale) {
    const __half2* p = (const __half2*)(q + (size_t)blockIdx.x * HD) + threadIdx.x * 2;
    float2 a = __half22float2(p[0]);
    float2 b = __half22float2(p[1]);
    float s = a.x * a.x + a.y * a.y + b.x * b.x + b.y * b.y;
    s = blk_reduce_256(s);
    if (threadIdx.x == 0) scale[blockIdx.x] = rsqrtf(s + 1e-6f) * 10.0f;
}

// fused fp32->fp16 copies: hidden (8192 blk) + Wk (1024) + Wo (1024)
__global__ void prep_copies(const float* __restrict__ hidden,
                            const float* __restrict__ Wk,
                            const float* __restrict__ Wo,
                            __half* __restrict__ ht,
                            __half* __restrict__ wk,
                            __half* __restrict__ wo) {
    const int b = blockIdx.x;
    const float* src;
    __half* dst;
    size_t blk;
    if (b < MQ) { src = hidden; dst = ht; blk = b; }
    else if (b < MQ + HD) { src = Wk; dst = wk; blk = b - MQ; }
    else { src = Wo; dst = wo; blk = b - MQ - HD; }
    const size_t i = blk * HD + threadIdx.x * 4;
    float4 v = *(const float4*)(src + i);
    __half2* o = (__half2*)(dst + i);
    o[0] = __floats2half2_rn(v.x, v.y);
    o[1] = __floats2half2_rn(v.z, v.w);
}

// ---------------------------------------------------------------------------

extern "C" void kernel_launch(void* const* d_in, const int* in_sizes, int n_in,
                              void* d_out, int out_size) {
    const float* hidden = (const float*)d_in[0];
    const float* Wk     = (const float*)d_in[1];
    const float* bk     = (const float*)d_in[2];
    const float* Wo     = (const float*)d_in[5];
    const float* bo     = (const float*)d_in[6];
    const float* mkeys  = (const float*)d_in[7];
    const float* mvals  = (const float*)d_in[8];
    const int*   usage  = (const int*)d_in[9];

    __half *mkn, *q, *P, *ret, *vt, *ht, *wk, *wo;
    float *qs, *rs, *part;
    cudaGetSymbolAddress((void**)&mkn, g_mkn);
    cudaGetSymbolAddress((void**)&q,   g_q);
    cudaGetSymbolAddress((void**)&qs,  g_qs);
    cudaGetSymbolAddress((void**)&P,   g_P);
    cudaGetSymbolAddress((void**)&rs,  g_rs);
    cudaGetSymbolAddress((void**)&ret, g_ret);
    cudaGetSymbolAddress((void**)&vt,  g_vt);
    cudaGetSymbolAddress((void**)&ht,  g_ht);
    cudaGetSymbolAddress((void**)&wk,  g_wk);
    cudaGetSymbolAddress((void**)&wo,  g_wo);
    cudaGetSymbolAddress((void**)&part, g_part);

    cudaFuncSetAttribute(gemm_mma<EPI_BIAS, true, false>,    cudaFuncAttributeMaxDynamicSharedMemorySize, SMEM_TOTAL);
    cudaFuncSetAttribute(gemm_mma<EPI_EXPMASK, true, false>, cudaFuncAttributeMaxDynamicSharedMemorySize, SMEM_TOTAL);
    cudaFuncSetAttribute(gemm_mma<EPI_NONE, false, true>,    cudaFuncAttributeMaxDynamicSharedMemorySize, SMEM_TOTAL);
    cudaFuncSetAttribute(gemm_mma<EPI_BIAS, false, false>,   cudaFuncAttributeMaxDynamicSharedMemorySize, SMEM_TOTAL);

    // fork a second stream for the gather track (capturable fork-join pattern;
    // stream/event objects are host-side — no device allocation)
    cudaStream_t s2;
    cudaStreamCreateWithFlags(&s2, cudaStreamNonBlocking);
    cudaEvent_t e1, e2;
    cudaEventCreateWithFlags(&e1, cudaEventDisableTiming);
    cudaEventCreateWithFlags(&e2, cudaEventDisableTiming);

    cudaEventRecord(e1, 0);
    cudaStreamWaitEvent(s2, e1, 0);

    // ---- track B (s2): compaction + gathers (independent of K2 chain) ----
    compact_mask<<<1, 256, 0, s2>>>(usage, rs);
    l2norm_gather<<<MMSZ, 256, 0, s2>>>(mkeys, mkn);
    transpose_gather<<<dim3(HD / 32, MMSZ / 32), dim3(32, 8), 0, s2>>>(mvals, vt);
    cudaEventRecord(e2, s2);

    // ---- track A (stream 0): copies -> K2 -> qscale ----
    prep_copies<<<MQ + 2 * HD, 256>>>(hidden, Wk, Wo, ht, wk, wo);

    // K2: q = fp16(X @ Wk^T + bk)
    gemm_mma<EPI_BIAS, true, false><<<dim3(MQ / BM, HD / BN), 256, SMEM_TOTAL>>>(
        ht, HD, wk, HD, q, HD, HD, bk, nullptr, 0);

    // K3: per-row query scale rsqrt(sumsq+eps)*10
    row_qscale<<<MQ, 256>>>(q, qs);

    // join: K4 needs mkn/mpad/rs from track B
    cudaStreamWaitEvent(0, e2, 0);

    // K4: P = fp16((col<mact) ? exp(dot*qs) : 0)  (+fused rowsums of rounded P)
    gemm_mma<EPI_EXPMASK, true, false><<<dim3(MQ / BM, MMSZ / BN), 256, SMEM_TOTAL>>>(
        q, HD, mkn, HD, P, MMSZ, HD, qs, rs, 0);

    // K6: split-K x4 fp32 partials of P @ Vt^T  (~99% wave util)
    gemm_mma<EPI_NONE, false, true><<<dim3(HD / BN, MQ / BM, SPLITK), 256, SMEM_TOTAL>>>(
        P, MMSZ, vt, MMSZ, part, HD, 0, nullptr, nullptr, 1);

    // K6b: ret = fp16((sum of partials) / rowsum)
    reduce_splitk<<<(MQ * HD) / 1024, 256>>>(part, rs, ret);

    // K7: out = ret @ Wo^T + bo  (fp32 out)
    gemm_mma<EPI_BIAS, false, false><<<dim3(MQ / BM, HD / BN), 256, SMEM_TOTAL>>>(
        ret, HD, wo, HD, (float*)d_out, HD, HD, bo, nullptr, 0);
}